// round 16
// baseline (speedup 1.0000x reference)
#include <cuda_runtime.h>
#include <cuda_fp16.h>
#include <cstdint>

#define S_LEN   2048
#define IN_DIM  512
#define OUT_DIM 512
#define NH      16
#define NKV     4
#define HD      64

// Q pre-scale: 1/sqrt(64) * log2(e)  (softmax done with ex2); folded into Wq.
#define SCALE_Q 0.18033688011112042f

// ---------------- scratch (__device__ globals; no cudaMalloc allowed) -------
__device__ __half g_xh[S_LEN * IN_DIM];            // x in fp16
__device__ __half g_wh[(NH * HD + 2 * NKV * HD) * IN_DIM];  // [Wq*s | Wk | Wv] fp16
__device__ __half g_woh[OUT_DIM * NH * HD];        // Wo fp16
__device__ __half g_qh[S_LEN * NH * HD];           // q fp16 (pre-scaled)
__device__ __half g_kh[S_LEN * NKV * HD];          // k fp16
__device__ __half g_vh[S_LEN * NKV * HD];          // v fp16
__device__ __half g_oparth[NKV][S_LEN * NH * HD];  // per-kv partials (fp16)
__device__ __half g_oh[S_LEN * NH * HD];           // reduced attention output fp16

__device__ __forceinline__ uint32_t ex2h2(uint32_t x) {
    uint32_t y; asm("ex2.approx.f16x2 %0, %1;" : "=r"(y) : "r"(x)); return y;
}
__device__ __forceinline__ uint32_t smem_u32(const void* p) {
    uint32_t a;
    asm("{ .reg .u64 t; cvta.to.shared.u64 t, %1; cvt.u32.u64 %0, t; }"
        : "=r"(a) : "l"(p));
    return a;
}
__device__ __forceinline__ uint64_t gmem_u64(const void* p) {
    uint64_t a;
    asm("cvta.to.global.u64 %0, %1;" : "=l"(a) : "l"(p));
    return a;
}

// m16n8k16 fp16 MMA, fp32 accumulate: C += A x B
__device__ __forceinline__ void mma16816(float* c, const uint32_t* a,
                                         uint32_t b0, uint32_t b1) {
    asm volatile(
        "mma.sync.aligned.m16n8k16.row.col.f32.f16.f16.f32 "
        "{%0,%1,%2,%3}, {%4,%5,%6,%7}, {%8,%9}, {%0,%1,%2,%3};"
        : "+f"(c[0]), "+f"(c[1]), "+f"(c[2]), "+f"(c[3])
        : "r"(a[0]), "r"(a[1]), "r"(a[2]), "r"(a[3]), "r"(b0), "r"(b1));
}
__device__ __forceinline__ void ldsm_x4(uint32_t& a, uint32_t& b, uint32_t& c,
                                        uint32_t& d, uint32_t addr) {
    asm volatile("ldmatrix.sync.aligned.m8n8.x4.shared.b16 {%0,%1,%2,%3}, [%4];"
                 : "=r"(a), "=r"(b), "=r"(c), "=r"(d) : "r"(addr));
}
__device__ __forceinline__ void ldsm_x4_t(uint32_t& a, uint32_t& b, uint32_t& c,
                                          uint32_t& d, uint32_t addr) {
    asm volatile("ldmatrix.sync.aligned.m8n8.x4.trans.shared.b16 {%0,%1,%2,%3}, [%4];"
                 : "=r"(a), "=r"(b), "=r"(c), "=r"(d) : "r"(addr));
}
__device__ __forceinline__ uint32_t packh2(float a, float b) {
    __half2 h = __floats2half2_rn(a, b);
    return *(uint32_t*)&h;
}

#define CP_ASYNC16(sm, gm) \
    asm volatile("cp.async.cg.shared.global [%0], [%1], 16;" :: "r"(sm), "l"(gm))
#define CP_COMMIT() asm volatile("cp.async.commit_group;" ::: "memory")
#define CP_WAIT0()  asm volatile("cp.async.wait_group 0;" ::: "memory")

// ---------------------------------------------------------------------------
// Fused fp32 -> fp16 convert for all 5 tensors. One float4 per thread.
// ---------------------------------------------------------------------------
__global__ __launch_bounds__(256)
void f2h_all_kernel(const float* __restrict__ x,  const float* __restrict__ wq,
                    const float* __restrict__ wk, const float* __restrict__ wv,
                    const float* __restrict__ wo)
{
    const int b = blockIdx.x;
    const float* src; __half* dst; int i; float scale = 1.0f;
    if (b < 1024)      { src = x;  dst = g_xh;  i = b * 256; }
    else if (b < 1536) { src = wq; dst = g_wh;  i = (b - 1024) * 256; scale = SCALE_Q; }
    else if (b < 1664) { src = wk; dst = g_wh + (NH * HD) * IN_DIM;            i = (b - 1536) * 256; }
    else if (b < 1792) { src = wv; dst = g_wh + (NH * HD + NKV * HD) * IN_DIM; i = (b - 1664) * 256; }
    else               { src = wo; dst = g_woh; i = (b - 1792) * 256; }
    i += threadIdx.x;
    float4 v = ((const float4*)src)[i];
    uint2 u = { packh2(v.x * scale, v.y * scale),
                packh2(v.z * scale, v.w * scale) };
    ((uint2*)dst)[i] = u;
}

// ---------------------------------------------------------------------------
// fp16 tensor-core GEMM body, cp.async double-buffered (R15, unchanged).
// ---------------------------------------------------------------------------
struct HEpiQkv {
    __half* C; int ldc;
    template <int NF>
    __device__ __forceinline__ void operator()(float (&acc)[NF][4], int row0, int lc) const {
        #pragma unroll
        for (int nf = 0; nf < NF; nf++) {
            int col = nf * 8 + lc * 2;
            *(uint32_t*)&C[(size_t)row0 * ldc + col]       = packh2(acc[nf][0], acc[nf][1]);
            *(uint32_t*)&C[(size_t)(row0 + 8) * ldc + col] = packh2(acc[nf][2], acc[nf][3]);
        }
    }
};
struct HEpiOut {
    float* C;
    template <int NF>
    __device__ __forceinline__ void operator()(float (&acc)[NF][4], int row0, int lc) const {
        #pragma unroll
        for (int nf = 0; nf < NF; nf++) {
            int col = nf * 8 + lc * 2;
            float2 u0 = { acc[nf][0], acc[nf][1] };
            float2 u1 = { acc[nf][2], acc[nf][3] };
            *(float2*)&C[(size_t)row0 * OUT_DIM + col]       = u0;
            *(float2*)&C[(size_t)(row0 + 8) * OUT_DIM + col] = u1;
        }
    }
};

template <int NF, class EPI>
__device__ __forceinline__ void hgemm_body(
    const __half* __restrict__ A, const __half* __restrict__ Bn,
    int K, int m0, EPI epi)
{
    __shared__ __align__(16) __half sA[2][64 * 72];
    __shared__ __align__(16) __half sB[2][NF * 8 * 72];
    constexpr int ABY = 64 * 72 * 2;
    constexpr int BBY = NF * 8 * 72 * 2;
    constexpr int PB  = NF * 64 / 128;

    const int tid = threadIdx.x;
    const int w = tid >> 5, l = tid & 31;
    const int g8 = l >> 3, r8 = l & 7;
    const int lr = l >> 2, lc = l & 3;

    const uint32_t aA = smem_u32(sA) +
        ((w * 16 + (g8 & 1) * 8 + r8) * 72 + (g8 >> 1) * 8) * 2;
    const uint32_t aB = smem_u32(sB) +
        (((g8 >> 1) * 8 + r8) * 72 + (g8 & 1) * 8) * 2;

    const int ra = (tid * 4) >> 3, ca = (tid * 4) & 7;
    const int rb = (tid * PB) >> 3, cb = (tid * PB) & 7;
    const uint64_t Ag0 = gmem_u64(A + (size_t)(m0 + ra) * K + ca * 8);
    const uint64_t Bg0 = gmem_u64(Bn + (size_t)rb * K + cb * 8);
    const uint32_t sAs = smem_u32(sA) + (ra * 72 + ca * 8) * 2;
    const uint32_t sBs = smem_u32(sB) + (rb * 72 + cb * 8) * 2;

    float acc[NF][4] = {};
    const int nch = K >> 6;

    #pragma unroll
    for (int j = 0; j < 4; j++)
        CP_ASYNC16(sAs + j * 16, Ag0 + (size_t)j * 16);
    #pragma unroll
    for (int j = 0; j < PB; j++)
        CP_ASYNC16(sBs + j * 16, Bg0 + (size_t)j * 16);
    CP_COMMIT();

    for (int kc = 0; kc < nch; kc++) {
        const int buf = kc & 1;
        CP_WAIT0();
        __syncthreads();

        if (kc + 1 < nch) {
            const uint64_t go = (size_t)(kc + 1) * 64 * 2;
            #pragma unroll
            for (int j = 0; j < 4; j++)
                CP_ASYNC16(sAs + (buf ^ 1) * ABY + j * 16, Ag0 + go + (size_t)j * 16);
            #pragma unroll
            for (int j = 0; j < PB; j++)
                CP_ASYNC16(sBs + (buf ^ 1) * BBY + j * 16, Bg0 + go + (size_t)j * 16);
            CP_COMMIT();
        }

        const uint32_t bA = aA + buf * ABY;
        const uint32_t bB = aB + buf * BBY;
        #pragma unroll
        for (int ks = 0; ks < 4; ks++) {
            uint32_t af[4];
            ldsm_x4(af[0], af[1], af[2], af[3], bA + ks * 16 * 2);
            #pragma unroll
            for (int ng = 0; ng < NF / 2; ng++) {
                uint32_t b0, b1, b2, b3;
                ldsm_x4(b0, b1, b2, b3, bB + (ng * 16 * 72 + ks * 16) * 2);
                mma16816(acc[2 * ng],     af, b0, b1);
                mma16816(acc[2 * ng + 1], af, b2, b3);
            }
        }
    }
    epi(acc, m0 + w * 16 + lr, lc);
}

// QKV projection (fp16 HMMA). grid (32, 24).
__global__ __launch_bounds__(128)
void qkv_kernel()
{
    const int by = blockIdx.y;
    const __half* Bn; __half* C; int ldc;
    if (by < 16) {
        Bn = g_wh + (size_t)(by * 64) * IN_DIM;
        C = g_qh + by * 64; ldc = NH * HD;
    } else if (by < 20) {
        Bn = g_wh + (size_t)(NH * HD + (by - 16) * 64) * IN_DIM;
        C = g_kh + (by - 16) * 64; ldc = NKV * HD;
    } else {
        Bn = g_wh + (size_t)(NH * HD + NKV * HD + (by - 20) * 64) * IN_DIM;
        C = g_vh + (by - 20) * 64; ldc = NKV * HD;
    }
    HEpiQkv epi = { C, ldc };
    hgemm_body<8>(g_xh, Bn, IN_DIM, blockIdx.x * 64, epi);
}

// Output projection (fp16 HMMA). grid (32, 16).
__global__ __launch_bounds__(128)
void out_gemm_kernel(float* __restrict__ out)
{
    const int n0 = blockIdx.y * 32;
    HEpiOut epi = { out + n0 };
    hgemm_body<4>(g_oh, g_woh + (size_t)n0 * (NH * HD), NH * HD, blockIdx.x * 64, epi);
}

// Sum fp16 kv partials (fp32 math) -> fp16 g_oh. uint4 (8 halves) / thread.
__global__ __launch_bounds__(256)
void reduce_o_kernel()
{
    int i = blockIdx.x * 256 + threadIdx.x;
    uint4 a = ((const uint4*)g_oparth[0])[i];
    uint4 b = ((const uint4*)g_oparth[1])[i];
    uint4 c = ((const uint4*)g_oparth[2])[i];
    uint4 d = ((const uint4*)g_oparth[3])[i];
    uint4 r;
    uint32_t* ap = (uint32_t*)&a; uint32_t* bp = (uint32_t*)&b;
    uint32_t* cp = (uint32_t*)&c; uint32_t* dp = (uint32_t*)&d;
    uint32_t* rp = (uint32_t*)&r;
    #pragma unroll
    for (int j = 0; j < 4; j++) {
        float2 fa = __half22float2(*(__half2*)&ap[j]);
        float2 fb = __half22float2(*(__half2*)&bp[j]);
        float2 fc = __half22float2(*(__half2*)&cp[j]);
        float2 fd = __half22float2(*(__half2*)&dp[j]);
        rp[j] = packh2(fa.x + fb.x + fc.x + fd.x,
                       fa.y + fb.y + fc.y + fd.y);
    }
    ((uint4*)g_oh)[i] = r;
}

// ---------------------------------------------------------------------------
// mma.sync flash attention (fp32-acc MMA, cp.async double-buffered K/V,
// ones-MMA row sums, fp16 partials). NEW: pack-then-exp softmax —
// 16x ex2.approx.f16x2 instead of 32x scalar ex2 (halves MUFU pressure);
// causal mask = bitwise AND on fp16 pairs, diagonal tile only.
// grid (32 s-blocks heavy-first, 16 h, 4 kv), 128 threads.
// ---------------------------------------------------------------------------
#define KP 72
#define BUFB (64 * KP * 2)       // bytes per K (or V) buffer
#define ONESF16 0x3C003C00u      // half2(1.0, 1.0)

__global__ __launch_bounds__(128)
void attn_kernel()
{
    __shared__ __align__(16) __half sK[2][64 * KP];
    __shared__ __align__(16) __half sV[2][64 * KP];

    const int tid = threadIdx.x;
    const int w   = tid >> 5;
    const int l   = tid & 31;
    const int lr  = l >> 2;
    const int lc  = l & 3;
    const int bs  = 31 - (int)blockIdx.x;   // heavy blocks first
    const int h   = blockIdx.y;
    const int kv  = blockIdx.z;
    const int s0  = bs * 64;
    const int T   = bs + 1;

    // ---- Q A-fragments, loaded once ---------------------------------------
    uint32_t qf[4][4];
    {
        const __half* qb = g_qh + (size_t)(s0 + w * 16) * (NH * HD) + h * HD;
        #pragma unroll
        for (int ks = 0; ks < 4; ks++) {
            int k0 = ks * 16 + lc * 2;
            qf[ks][0] = *(const uint32_t*)(qb + (size_t)lr * (NH * HD) + k0);
            qf[ks][1] = *(const uint32_t*)(qb + (size_t)(lr + 8) * (NH * HD) + k0);
            qf[ks][2] = *(const uint32_t*)(qb + (size_t)lr * (NH * HD) + k0 + 8);
            qf[ks][3] = *(const uint32_t*)(qb + (size_t)(lr + 8) * (NH * HD) + k0 + 8);
        }
    }

    const int g8 = l >> 3, r8 = l & 7;
    const uint32_t aK = smem_u32(sK) +
        (((g8 >> 1) * 8 + r8) * KP + (g8 & 1) * 8) * 2;
    const uint32_t aV = smem_u32(sV) +
        (((g8 & 1) * 8 + r8) * KP + (g8 >> 1) * 8) * 2;

    float oacc[8][4] = {};
    float lacc[4] = {};                     // ones-MMA row sums
    const int row0 = s0 + w * 16 + lr;
    const int row1 = row0 + 8;

    // K/V stager: thread covers half a row (64 B) of each tile. cp.async x8.
    const int key = tid >> 1, hf = tid & 1;
    const uint64_t kg0 = gmem_u64(g_kh + (size_t)key * (NKV * HD) + kv * HD + hf * 32);
    const uint64_t vg0 = gmem_u64(g_vh + (size_t)key * (NKV * HD) + kv * HD + hf * 32);
    const uint32_t sk0 = smem_u32(sK) + (key * KP + hf * 32) * 2;
    const uint32_t sv0 = smem_u32(sV) + (key * KP + hf * 32) * 2;

    // prologue: stage tile 0 into buffer 0
    #pragma unroll
    for (int j = 0; j < 4; j++) {
        CP_ASYNC16(sk0 + j * 16, kg0 + j * 16);
        CP_ASYNC16(sv0 + j * 16, vg0 + j * 16);
    }
    CP_COMMIT();

    for (int t = 0; t < T; t++) {
        const int buf = t & 1;
        CP_WAIT0();            // tile t landed (only outstanding group)
        __syncthreads();       // visible to all; all reads of buf^1 done

        // stage tile t+1 into the other buffer (race-free: after barrier)
        if (t + 1 < T) {
            const uint64_t kg = kg0 + (size_t)(t + 1) * 64 * (NKV * HD) * 2;
            const uint64_t vg = vg0 + (size_t)(t + 1) * 64 * (NKV * HD) * 2;
            const uint32_t sk = sk0 + (buf ^ 1) * BUFB;
            const uint32_t sv = sv0 + (buf ^ 1) * BUFB;
            #pragma unroll
            for (int j = 0; j < 4; j++) {
                CP_ASYNC16(sk + j * 16, kg + j * 16);
                CP_ASYNC16(sv + j * 16, vg + j * 16);
            }
            CP_COMMIT();
        }

        const uint32_t bK = aK + buf * BUFB;
        const uint32_t bV = aV + buf * BUFB;

        // ---- S = Q K^T (fp32 accumulate) ----------------------------------
        float sc[8][4] = {};
        #pragma unroll
        for (int ks = 0; ks < 4; ks++) {
            #pragma unroll
            for (int kg2 = 0; kg2 < 4; kg2++) {
                uint32_t b0, b1, b2, b3;
                ldsm_x4(b0, b1, b2, b3, bK + (kg2 * 16 * KP + ks * 16) * 2);
                mma16816(sc[2 * kg2],     qf[ks], b0, b1);
                mma16816(sc[2 * kg2 + 1], qf[ks], b2, b3);
            }
        }

        // ---- pack-then-exp softmax (f16x2 MUFU, un-normalized) ------------
        // pf[nf>>1][(nf&1)*2+0] = exp2(pack(sc[nf][0], sc[nf][1]))  (row0 pair)
        // pf[nf>>1][(nf&1)*2+1] = exp2(pack(sc[nf][2], sc[nf][3]))  (row1 pair)
        uint32_t pf[4][4];
        #pragma unroll
        for (int nf = 0; nf < 8; nf++) {
            pf[nf >> 1][(nf & 1) * 2 + 0] = ex2h2(packh2(sc[nf][0], sc[nf][1]));
            pf[nf >> 1][(nf & 1) * 2 + 1] = ex2h2(packh2(sc[nf][2], sc[nf][3]));
        }
        if (t == T - 1) {
            const int jb = t * 64;
            #pragma unroll
            for (int nf = 0; nf < 8; nf++) {
                int j0 = jb + nf * 8 + lc * 2;
                uint32_t m0 = (j0 <= row0 ? 0x0000FFFFu : 0u) |
                              (j0 + 1 <= row0 ? 0xFFFF0000u : 0u);
                uint32_t m1 = (j0 <= row1 ? 0x0000FFFFu : 0u) |
                              (j0 + 1 <= row1 ? 0xFFFF0000u : 0u);
                pf[nf >> 1][(nf & 1) * 2 + 0] &= m0;
                pf[nf >> 1][(nf & 1) * 2 + 1] &= m1;
            }
        }

        // ---- O += P V, lsum += P @ ones -----------------------------------
        #pragma unroll
        for (int ksg = 0; ksg < 4; ksg++) {
            mma16816(lacc, pf[ksg], ONESF16, ONESF16);
            #pragma unroll
            for (int nfp = 0; nfp < 4; nfp++) {
                uint32_t b0, b1, b2, b3;
                ldsm_x4_t(b0, b1, b2, b3, bV + (ksg * 16 * KP + nfp * 16) * 2);
                mma16816(oacc[2 * nfp],     pf[ksg], b0, b1);
                mma16816(oacc[2 * nfp + 1], pf[ksg], b2, b3);
            }
        }
    }

    // lacc holds full cross-lane row sums (MMA reduces over k)
    const float inv0 = 0.25f / lacc[0];
    const float inv1 = 0.25f / lacc[2];

    __half* d0 = g_oparth[kv] + (size_t)row0 * (NH * HD) + h * HD + lc * 2;
    __half* d1 = g_oparth[kv] + (size_t)row1 * (NH * HD) + h * HD + lc * 2;
    #pragma unroll
    for (int df = 0; df < 8; df++) {
        *(uint32_t*)(d0 + df * 8) = packh2(oacc[df][0] * inv0, oacc[df][1] * inv0);
        *(uint32_t*)(d1 + df * 8) = packh2(oacc[df][2] * inv1, oacc[df][3] * inv1);
    }
}

// ---------------------------------------------------------------------------
extern "C" void kernel_launch(void* const* d_in, const int* in_sizes, int n_in,
                              void* d_out, int out_size)
{
    const float* x  = (const float*)d_in[0];
    const float* Wq = (const float*)d_in[1];
    const float* Wk = (const float*)d_in[2];
    const float* Wv = (const float*)d_in[3];
    const float* Wo = (const float*)d_in[4];
    float* out = (float*)d_out;

    f2h_all_kernel<<<2304, 256>>>(x, Wq, Wk, Wv, Wo);
    qkv_kernel<<<dim3(32, 24), 128>>>();
    attn_kernel<<<dim3(32, 16, 4), 128>>>();
    reduce_o_kernel<<<1024, 256>>>();
    out_gemm_kernel<<<dim3(32, 16), 128>>>(out);
}

// round 17
// speedup vs baseline: 1.0482x; 1.0482x over previous
#include <cuda_runtime.h>
#include <cuda_fp16.h>
#include <cstdint>

#define S_LEN   2048
#define IN_DIM  512
#define OUT_DIM 512
#define NH      16
#define NKV     4
#define HD      64

// Q pre-scale: 1/sqrt(64) * log2(e)  (softmax done with ex2); folded into Wq.
#define SCALE_Q 0.18033688011112042f

// ---------------- scratch (__device__ globals; no cudaMalloc allowed) -------
__device__ __half g_xh[S_LEN * IN_DIM];            // x in fp16
__device__ __half g_wh[(NH * HD + 2 * NKV * HD) * IN_DIM];  // [Wq*s | Wk | Wv] fp16
__device__ __half g_woh[OUT_DIM * NH * HD];        // Wo fp16
__device__ __half g_qh[S_LEN * NH * HD];           // q fp16 (pre-scaled)
__device__ __half g_kh[S_LEN * NKV * HD];          // k fp16
__device__ __half g_vh[S_LEN * NKV * HD];          // v fp16
__device__ __half g_oh[S_LEN * NH * HD];           // attention output fp16 (atomic-acc)

__device__ __forceinline__ float ex2f(float x) {
    float y; asm("ex2.approx.ftz.f32 %0, %1;" : "=f"(y) : "f"(x)); return y;
}
__device__ __forceinline__ uint32_t smem_u32(const void* p) {
    uint32_t a;
    asm("{ .reg .u64 t; cvta.to.shared.u64 t, %1; cvt.u32.u64 %0, t; }"
        : "=r"(a) : "l"(p));
    return a;
}
__device__ __forceinline__ uint64_t gmem_u64(const void* p) {
    uint64_t a;
    asm("cvta.to.global.u64 %0, %1;" : "=l"(a) : "l"(p));
    return a;
}

// m16n8k16 fp16 MMA, fp32 accumulate: C += A x B
__device__ __forceinline__ void mma16816(float* c, const uint32_t* a,
                                         uint32_t b0, uint32_t b1) {
    asm volatile(
        "mma.sync.aligned.m16n8k16.row.col.f32.f16.f16.f32 "
        "{%0,%1,%2,%3}, {%4,%5,%6,%7}, {%8,%9}, {%0,%1,%2,%3};"
        : "+f"(c[0]), "+f"(c[1]), "+f"(c[2]), "+f"(c[3])
        : "r"(a[0]), "r"(a[1]), "r"(a[2]), "r"(a[3]), "r"(b0), "r"(b1));
}
__device__ __forceinline__ void ldsm_x4(uint32_t& a, uint32_t& b, uint32_t& c,
                                        uint32_t& d, uint32_t addr) {
    asm volatile("ldmatrix.sync.aligned.m8n8.x4.shared.b16 {%0,%1,%2,%3}, [%4];"
                 : "=r"(a), "=r"(b), "=r"(c), "=r"(d) : "r"(addr));
}
__device__ __forceinline__ void ldsm_x4_t(uint32_t& a, uint32_t& b, uint32_t& c,
                                          uint32_t& d, uint32_t addr) {
    asm volatile("ldmatrix.sync.aligned.m8n8.x4.trans.shared.b16 {%0,%1,%2,%3}, [%4];"
                 : "=r"(a), "=r"(b), "=r"(c), "=r"(d) : "r"(addr));
}
__device__ __forceinline__ uint32_t packh2(float a, float b) {
    __half2 h = __floats2half2_rn(a, b);
    return *(uint32_t*)&h;
}
__device__ __forceinline__ void red_f16x2(uint64_t gaddr, uint32_t v) {
    asm volatile("red.global.add.noftz.f16x2 [%0], %1;" :: "l"(gaddr), "r"(v) : "memory");
}
__device__ __forceinline__ void red_f32(uint64_t gaddr, float v) {
    asm volatile("red.global.add.f32 [%0], %1;" :: "l"(gaddr), "f"(v) : "memory");
}

#define CP_ASYNC16(sm, gm) \
    asm volatile("cp.async.cg.shared.global [%0], [%1], 16;" :: "r"(sm), "l"(gm))
#define CP_COMMIT() asm volatile("cp.async.commit_group;" ::: "memory")
#define CP_WAIT0()  asm volatile("cp.async.wait_group 0;" ::: "memory")

// ---------------------------------------------------------------------------
// Fused fp32->fp16 convert for all 5 tensors + zeroing of `out` and g_oh.
// One 16B unit per thread. Block map:
//   [0,1024) x | [1024,1536) Wq | [1536,1664) Wk | [1664,1792) Wv |
//   [1792,2304) Wo | [2304,3328) zero out (fp32) | [3328,4352) zero g_oh
// ---------------------------------------------------------------------------
__global__ __launch_bounds__(256)
void f2h_all_kernel(const float* __restrict__ x,  const float* __restrict__ wq,
                    const float* __restrict__ wk, const float* __restrict__ wv,
                    const float* __restrict__ wo, float* __restrict__ out)
{
    const int b = blockIdx.x;
    if (b >= 2304) {
        uint4 z = {0u, 0u, 0u, 0u};
        if (b < 3328) ((uint4*)out)[(b - 2304) * 256 + threadIdx.x] = z;
        else          ((uint4*)g_oh)[(b - 3328) * 256 + threadIdx.x] = z;
        return;
    }
    const float* src; __half* dst; int i; float scale = 1.0f;
    if (b < 1024)      { src = x;  dst = g_xh;  i = b * 256; }
    else if (b < 1536) { src = wq; dst = g_wh;  i = (b - 1024) * 256; scale = SCALE_Q; }
    else if (b < 1664) { src = wk; dst = g_wh + (NH * HD) * IN_DIM;            i = (b - 1536) * 256; }
    else if (b < 1792) { src = wv; dst = g_wh + (NH * HD + NKV * HD) * IN_DIM; i = (b - 1664) * 256; }
    else               { src = wo; dst = g_woh; i = (b - 1792) * 256; }
    i += threadIdx.x;
    float4 v = ((const float4*)src)[i];
    uint2 u = { packh2(v.x * scale, v.y * scale),
                packh2(v.z * scale, v.w * scale) };
    ((uint2*)dst)[i] = u;
}

// ---------------------------------------------------------------------------
// fp16 tensor-core GEMM body, cp.async double-buffered. ldk = row stride of
// A and Bn (elements); nch = number of 64-wide k-chunks to consume.
// ---------------------------------------------------------------------------
struct HEpiQkv {
    __half* C; int ldc;
    template <int NF>
    __device__ __forceinline__ void operator()(float (&acc)[NF][4], int row0, int lc) const {
        #pragma unroll
        for (int nf = 0; nf < NF; nf++) {
            int col = nf * 8 + lc * 2;
            *(uint32_t*)&C[(size_t)row0 * ldc + col]       = packh2(acc[nf][0], acc[nf][1]);
            *(uint32_t*)&C[(size_t)(row0 + 8) * ldc + col] = packh2(acc[nf][2], acc[nf][3]);
        }
    }
};
// split-K: atomically accumulate fp32 partials into out
struct HEpiOutAtomic {
    float* C;
    template <int NF>
    __device__ __forceinline__ void operator()(float (&acc)[NF][4], int row0, int lc) const {
        const uint64_t b0 = gmem_u64(C + (size_t)row0 * OUT_DIM + lc * 2);
        const uint64_t b1 = gmem_u64(C + (size_t)(row0 + 8) * OUT_DIM + lc * 2);
        #pragma unroll
        for (int nf = 0; nf < NF; nf++) {
            red_f32(b0 + nf * 32,     acc[nf][0]);
            red_f32(b0 + nf * 32 + 4, acc[nf][1]);
            red_f32(b1 + nf * 32,     acc[nf][2]);
            red_f32(b1 + nf * 32 + 4, acc[nf][3]);
        }
    }
};

template <int NF, class EPI>
__device__ __forceinline__ void hgemm_body(
    const __half* __restrict__ A, const __half* __restrict__ Bn,
    int ldk, int nch, int m0, EPI epi)
{
    __shared__ __align__(16) __half sA[2][64 * 72];
    __shared__ __align__(16) __half sB[2][NF * 8 * 72];
    constexpr int ABY = 64 * 72 * 2;
    constexpr int BBY = NF * 8 * 72 * 2;
    constexpr int PB  = NF * 64 / 128;

    const int tid = threadIdx.x;
    const int w = tid >> 5, l = tid & 31;
    const int g8 = l >> 3, r8 = l & 7;
    const int lr = l >> 2, lc = l & 3;

    const uint32_t aA = smem_u32(sA) +
        ((w * 16 + (g8 & 1) * 8 + r8) * 72 + (g8 >> 1) * 8) * 2;
    const uint32_t aB = smem_u32(sB) +
        (((g8 >> 1) * 8 + r8) * 72 + (g8 & 1) * 8) * 2;

    const int ra = (tid * 4) >> 3, ca = (tid * 4) & 7;
    const int rb = (tid * PB) >> 3, cb = (tid * PB) & 7;
    const uint64_t Ag0 = gmem_u64(A + (size_t)(m0 + ra) * ldk + ca * 8);
    const uint64_t Bg0 = gmem_u64(Bn + (size_t)rb * ldk + cb * 8);
    const uint32_t sAs = smem_u32(sA) + (ra * 72 + ca * 8) * 2;
    const uint32_t sBs = smem_u32(sB) + (rb * 72 + cb * 8) * 2;

    float acc[NF][4] = {};

    #pragma unroll
    for (int j = 0; j < 4; j++)
        CP_ASYNC16(sAs + j * 16, Ag0 + (size_t)j * 16);
    #pragma unroll
    for (int j = 0; j < PB; j++)
        CP_ASYNC16(sBs + j * 16, Bg0 + (size_t)j * 16);
    CP_COMMIT();

    for (int kc = 0; kc < nch; kc++) {
        const int buf = kc & 1;
        CP_WAIT0();
        __syncthreads();

        if (kc + 1 < nch) {
            const uint64_t go = (size_t)(kc + 1) * 64 * 2;
            #pragma unroll
            for (int j = 0; j < 4; j++)
                CP_ASYNC16(sAs + (buf ^ 1) * ABY + j * 16, Ag0 + go + (size_t)j * 16);
            #pragma unroll
            for (int j = 0; j < PB; j++)
                CP_ASYNC16(sBs + (buf ^ 1) * BBY + j * 16, Bg0 + go + (size_t)j * 16);
            CP_COMMIT();
        }

        const uint32_t bA = aA + buf * ABY;
        const uint32_t bB = aB + buf * BBY;
        #pragma unroll
        for (int ks = 0; ks < 4; ks++) {
            uint32_t af[4];
            ldsm_x4(af[0], af[1], af[2], af[3], bA + ks * 16 * 2);
            #pragma unroll
            for (int ng = 0; ng < NF / 2; ng++) {
                uint32_t b0, b1, b2, b3;
                ldsm_x4(b0, b1, b2, b3, bB + (ng * 16 * 72 + ks * 16) * 2);
                mma16816(acc[2 * ng],     af, b0, b1);
                mma16816(acc[2 * ng + 1], af, b2, b3);
            }
        }
    }
    epi(acc, m0 + w * 16 + lr, lc);
}

// QKV projection (fp16 HMMA). grid (32, 24).
__global__ __launch_bounds__(128)
void qkv_kernel()
{
    const int by = blockIdx.y;
    const __half* Bn; __half* C; int ldc;
    if (by < 16) {
        Bn = g_wh + (size_t)(by * 64) * IN_DIM;
        C = g_qh + by * 64; ldc = NH * HD;
    } else if (by < 20) {
        Bn = g_wh + (size_t)(NH * HD + (by - 16) * 64) * IN_DIM;
        C = g_kh + (by - 16) * 64; ldc = NKV * HD;
    } else {
        Bn = g_wh + (size_t)(NH * HD + NKV * HD + (by - 20) * 64) * IN_DIM;
        C = g_vh + (by - 20) * 64; ldc = NKV * HD;
    }
    HEpiQkv epi = { C, ldc };
    hgemm_body<8>(g_xh, Bn, IN_DIM, IN_DIM / 64, blockIdx.x * 64, epi);
}

// Output projection (fp16 HMMA), split-K. grid (32, 16, 2).
// z selects k-half: columns [z*512, z*512+512) of g_oh / Wo.
__global__ __launch_bounds__(128)
void out_gemm_kernel(float* __restrict__ out)
{
    const int n0 = blockIdx.y * 32;
    const int z  = blockIdx.z;
    HEpiOutAtomic epi = { out + n0 };
    hgemm_body<4>(g_oh + z * 512,
                  g_woh + (size_t)n0 * (NH * HD) + z * 512,
                  NH * HD, 8, blockIdx.x * 64, epi);
}

// ---------------------------------------------------------------------------
// mma.sync flash attention (R15 version: fp32-acc MMA, scalar ex2, cp.async
// double-buffered K/V, one sync per tile, ones-MMA row sums).
// Epilogue: red.global.add.f16x2 of normalized per-kv output into g_oh.
// grid (32 s-blocks heavy-first, 16 h, 4 kv), 128 threads.
// ---------------------------------------------------------------------------
#define KP 72
#define BUFB (64 * KP * 2)       // bytes per K (or V) buffer
#define ONESF16 0x3C003C00u      // half2(1.0, 1.0)

__global__ __launch_bounds__(128)
void attn_kernel()
{
    __shared__ __align__(16) __half sK[2][64 * KP];
    __shared__ __align__(16) __half sV[2][64 * KP];

    const int tid = threadIdx.x;
    const int w   = tid >> 5;
    const int l   = tid & 31;
    const int lr  = l >> 2;
    const int lc  = l & 3;
    const int bs  = 31 - (int)blockIdx.x;   // heavy blocks first
    const int h   = blockIdx.y;
    const int kv  = blockIdx.z;
    const int s0  = bs * 64;
    const int T   = bs + 1;

    // ---- Q A-fragments, loaded once ---------------------------------------
    uint32_t qf[4][4];
    {
        const __half* qb = g_qh + (size_t)(s0 + w * 16) * (NH * HD) + h * HD;
        #pragma unroll
        for (int ks = 0; ks < 4; ks++) {
            int k0 = ks * 16 + lc * 2;
            qf[ks][0] = *(const uint32_t*)(qb + (size_t)lr * (NH * HD) + k0);
            qf[ks][1] = *(const uint32_t*)(qb + (size_t)(lr + 8) * (NH * HD) + k0);
            qf[ks][2] = *(const uint32_t*)(qb + (size_t)lr * (NH * HD) + k0 + 8);
            qf[ks][3] = *(const uint32_t*)(qb + (size_t)(lr + 8) * (NH * HD) + k0 + 8);
        }
    }

    const int g8 = l >> 3, r8 = l & 7;
    const uint32_t aK = smem_u32(sK) +
        (((g8 >> 1) * 8 + r8) * KP + (g8 & 1) * 8) * 2;
    const uint32_t aV = smem_u32(sV) +
        (((g8 & 1) * 8 + r8) * KP + (g8 >> 1) * 8) * 2;

    float oacc[8][4] = {};
    float lacc[4] = {};                     // ones-MMA row sums
    const int row0 = s0 + w * 16 + lr;
    const int row1 = row0 + 8;

    // K/V stager: thread covers half a row (64 B) of each tile. cp.async x8.
    const int key = tid >> 1, hf = tid & 1;
    const uint64_t kg0 = gmem_u64(g_kh + (size_t)key * (NKV * HD) + kv * HD + hf * 32);
    const uint64_t vg0 = gmem_u64(g_vh + (size_t)key * (NKV * HD) + kv * HD + hf * 32);
    const uint32_t sk0 = smem_u32(sK) + (key * KP + hf * 32) * 2;
    const uint32_t sv0 = smem_u32(sV) + (key * KP + hf * 32) * 2;

    // prologue: stage tile 0 into buffer 0
    #pragma unroll
    for (int j = 0; j < 4; j++) {
        CP_ASYNC16(sk0 + j * 16, kg0 + j * 16);
        CP_ASYNC16(sv0 + j * 16, vg0 + j * 16);
    }
    CP_COMMIT();

    for (int t = 0; t < T; t++) {
        const int buf = t & 1;
        CP_WAIT0();            // tile t landed (only outstanding group)
        __syncthreads();       // visible to all; all reads of buf^1 done

        // stage tile t+1 into the other buffer (race-free: after barrier)
        if (t + 1 < T) {
            const uint64_t kg = kg0 + (size_t)(t + 1) * 64 * (NKV * HD) * 2;
            const uint64_t vg = vg0 + (size_t)(t + 1) * 64 * (NKV * HD) * 2;
            const uint32_t sk = sk0 + (buf ^ 1) * BUFB;
            const uint32_t sv = sv0 + (buf ^ 1) * BUFB;
            #pragma unroll
            for (int j = 0; j < 4; j++) {
                CP_ASYNC16(sk + j * 16, kg + j * 16);
                CP_ASYNC16(sv + j * 16, vg + j * 16);
            }
            CP_COMMIT();
        }

        const uint32_t bK = aK + buf * BUFB;
        const uint32_t bV = aV + buf * BUFB;

        // ---- S = Q K^T ----------------------------------------------------
        float sc[8][4] = {};
        #pragma unroll
        for (int ks = 0; ks < 4; ks++) {
            #pragma unroll
            for (int kg2 = 0; kg2 < 4; kg2++) {
                uint32_t b0, b1, b2, b3;
                ldsm_x4(b0, b1, b2, b3, bK + (kg2 * 16 * KP + ks * 16) * 2);
                mma16816(sc[2 * kg2],     qf[ks], b0, b1);
                mma16816(sc[2 * kg2 + 1], qf[ks], b2, b3);
            }
        }

        // ---- exp (un-normalized); mask only on diagonal tile --------------
        uint32_t pf[4][4];
        if (t < T - 1) {
            #pragma unroll
            for (int nf = 0; nf < 8; nf++) {
                float p00 = ex2f(sc[nf][0]);
                float p01 = ex2f(sc[nf][1]);
                float p10 = ex2f(sc[nf][2]);
                float p11 = ex2f(sc[nf][3]);
                pf[nf >> 1][(nf & 1) * 2 + 0] = packh2(p00, p01);
                pf[nf >> 1][(nf & 1) * 2 + 1] = packh2(p10, p11);
            }
        } else {
            const int jb = t * 64;
            #pragma unroll
            for (int nf = 0; nf < 8; nf++) {
                int j0 = jb + nf * 8 + lc * 2;
                float p00 = (j0     <= row0) ? ex2f(sc[nf][0]) : 0.f;
                float p01 = (j0 + 1 <= row0) ? ex2f(sc[nf][1]) : 0.f;
                float p10 = (j0     <= row1) ? ex2f(sc[nf][2]) : 0.f;
                float p11 = (j0 + 1 <= row1) ? ex2f(sc[nf][3]) : 0.f;
                pf[nf >> 1][(nf & 1) * 2 + 0] = packh2(p00, p01);
                pf[nf >> 1][(nf & 1) * 2 + 1] = packh2(p10, p11);
            }
        }

        // ---- O += P V, lsum += P @ ones -----------------------------------
        #pragma unroll
        for (int ksg = 0; ksg < 4; ksg++) {
            mma16816(lacc, pf[ksg], ONESF16, ONESF16);
            #pragma unroll
            for (int nfp = 0; nfp < 4; nfp++) {
                uint32_t b0, b1, b2, b3;
                ldsm_x4_t(b0, b1, b2, b3, bV + (ksg * 16 * KP + nfp * 16) * 2);
                mma16816(oacc[2 * nfp],     pf[ksg], b0, b1);
                mma16816(oacc[2 * nfp + 1], pf[ksg], b2, b3);
            }
        }
    }

    // lacc holds full cross-lane row sums (MMA reduces over k)
    const float inv0 = 0.25f / lacc[0];
    const float inv1 = 0.25f / lacc[2];

    // ---- atomically fold normalized per-kv output into g_oh ---------------
    const uint64_t a0 = gmem_u64(g_oh + (size_t)row0 * (NH * HD) + h * HD + lc * 2);
    const uint64_t a1 = gmem_u64(g_oh + (size_t)row1 * (NH * HD) + h * HD + lc * 2);
    #pragma unroll
    for (int df = 0; df < 8; df++) {
        red_f16x2(a0 + df * 16, packh2(oacc[df][0] * inv0, oacc[df][1] * inv0));
        red_f16x2(a1 + df * 16, packh2(oacc[df][2] * inv1, oacc[df][3] * inv1));
    }
}

// ---------------------------------------------------------------------------
extern "C" void kernel_launch(void* const* d_in, const int* in_sizes, int n_in,
                              void* d_out, int out_size)
{
    const float* x  = (const float*)d_in[0];
    const float* Wq = (const float*)d_in[1];
    const float* Wk = (const float*)d_in[2];
    const float* Wv = (const float*)d_in[3];
    const float* Wo = (const float*)d_in[4];
    float* out = (float*)d_out;

    f2h_all_kernel<<<4352, 256>>>(x, Wq, Wk, Wv, Wo, out);
    qkv_kernel<<<dim3(32, 24), 128>>>();
    attn_kernel<<<dim3(32, 16, 4), 128>>>();
    out_gemm_kernel<<<dim3(32, 16, 2), 128>>>(out);
}